// round 1
// baseline (speedup 1.0000x reference)
#include <cuda_runtime.h>

#define FULL_MASK 0xFFFFFFFFu

// Precomputed variational-layer cos/sin (layers 1,2 of 3; layer 0 folds into
// encoding) and folded layer-0 half-angle offsets. Written by quanv_prep.
__device__ float d_vc[2][3][9];
__device__ float d_vs[2][3][9];
__device__ float d_h0[3][9];

__global__ void quanv_prep(const float* __restrict__ qp) {
    int t = threadIdx.x;
    if (t < 27) {
        int c = t / 9, q = t % 9;
        d_h0[c][q] = 0.5f * qp[c * 16 + q];          // q_params[0, c, q]
    } else if (t < 81) {
        int u = t - 27;
        int l = u / 27;                               // 0 -> layer1, 1 -> layer2
        int c = (u % 27) / 9;
        int q = u % 9;
        float s, co;
        __sincosf(0.5f * qp[((l + 1) * 3 + c) * 16 + q], &s, &co);
        d_vc[l][c][q] = co;
        d_vs[l][c][q] = s;
    }
}

// One warp simulates one (b,h,w,c) site: 512 real amplitudes = 32 lanes x 16 regs.
// Qubit q <-> bit (8-q) of the amplitude index; qubits 0-4 are lane bits
// (lane bit 4-q), qubits 5-8 are register-index bits (reg bit 8-q).
__global__ void __launch_bounds__(256)
quanv_main(const float* __restrict__ x, float* __restrict__ out) {
    const int lane = threadIdx.x & 31;
    const int site = (blockIdx.x * 256 + threadIdx.x) >> 5;  // grid sized exactly
    const int c   = site % 3;
    const int sw  = (site / 3) & 31;
    const int shh = (site / 96) & 31;
    const int b   = site / 3072;

    // --- Encoding: RY(pi*pixel) with layer-0 variational RY folded in ---
    float ec[9], es[9];
#pragma unroll
    for (int q = 0; q < 9; ++q) {
        const int di = q / 3 - 1, dj = q % 3 - 1;
        const int hi = shh + di, wj = sw + dj;
        float px = 0.0f;
        if ((unsigned)hi < 32u && (unsigned)wj < 32u)
            px = x[((b * 32 + hi) * 32 + wj) * 3 + c];
        __sincosf(fmaf(1.5707963267948966f, px, d_h0[c][q]), &es[q], &ec[q]);
    }

    // --- Product state with layer-0 CNOT ring folded in as a GF(2) index map:
    // amp[c-bits] = prod_q F_q(b_q),  b0=c0^c8, b1=c1^c0^c8, bq=cq^c(q-1). ---
    const int c0 = (lane >> 4) & 1, c1 = (lane >> 3) & 1, c2 = (lane >> 2) & 1,
              c3 = (lane >> 1) & 1, c4 = lane & 1;
    const float Pb = ((c2 ^ c1) ? es[2] : ec[2]) * ((c3 ^ c2) ? es[3] : ec[3]) *
                     ((c4 ^ c3) ? es[4] : ec[4]);
    const float P0 = Pb * (c0 ? es[0] : ec[0]) * ((c1 ^ c0) ? es[1] : ec[1]); // c8=0
    const float P1 = Pb * (c0 ? ec[0] : es[0]) * ((c1 ^ c0) ? ec[1] : es[1]); // c8=1
    const float G0 = c4 ? es[5] : ec[5];  // c5=0 -> b5=c4
    const float G1 = c4 ? ec[5] : es[5];  // c5=1 -> b5=1^c4

    float st[16];
#pragma unroll
    for (int r = 0; r < 16; ++r) {
        const int r5 = (r >> 3) & 1, r6 = (r >> 2) & 1, r7 = (r >> 1) & 1, r8 = r & 1;
        float v = (r8 ? P1 : P0) * (r5 ? G1 : G0);
        v *= (r6 ^ r5) ? es[6] : ec[6];
        v *= (r7 ^ r6) ? es[7] : ec[7];
        v *= (r8 ^ r7) ? es[8] : ec[8];
        st[r] = v;
    }

    // --- Two explicit variational layers (layers 1,2). Layer 1 keeps its CNOT
    // ring; layer 2's ring is folded into the measurement sign masks. ---
#pragma unroll
    for (int l = 0; l < 2; ++l) {
        // RYs on lane-bit qubits 0..4 (warp shuffles)
#pragma unroll
        for (int q = 0; q < 5; ++q) {
            const int m = 1 << (4 - q);
            const float vcq = d_vc[l][c][q];
            const float vsq = d_vs[l][c][q];
            const float svs = (lane & m) ? vsq : -vsq;
#pragma unroll
            for (int r = 0; r < 16; ++r) {
                const float p = __shfl_xor_sync(FULL_MASK, st[r], m);
                st[r] = fmaf(vcq, st[r], svs * p);
            }
        }
        // RYs on register-bit qubits 5..8 (pure register math)
#pragma unroll
        for (int q = 5; q < 9; ++q) {
            const int m = 1 << (8 - q);
            const float vcq = d_vc[l][c][q];
            const float vsq = d_vs[l][c][q];
#pragma unroll
            for (int r = 0; r < 16; ++r)
                if (!(r & m)) {
                    const float a0 = st[r], a1 = st[r + m];
                    st[r]     = fmaf(vcq, a0, -vsq * a1);
                    st[r + m] = fmaf(vcq, a1,  vsq * a0);
                }
        }

        if (l == 0) {
            // CNOT ring, qubits q -> q+1
            // q=0..3: ctrl lane bit, tgt lane bit
#pragma unroll
            for (int q = 0; q < 4; ++q) {
                const int cm = 1 << (4 - q), tm = 1 << (3 - q);
                const bool hi = (lane & cm) != 0;
#pragma unroll
                for (int r = 0; r < 16; ++r) {
                    const float p = __shfl_xor_sync(FULL_MASK, st[r], tm);
                    st[r] = hi ? p : st[r];
                }
            }
            // q=4: ctrl lane bit 0, tgt reg bit 3 (predicated register swap)
            {
                const bool hi = (lane & 1) != 0;
#pragma unroll
                for (int r = 0; r < 8; ++r) {
                    const float a = st[r], bb = st[r + 8];
                    st[r]     = hi ? bb : a;
                    st[r + 8] = hi ? a : bb;
                }
            }
            // q=5..7: ctrl reg bit, tgt reg bit — compile-time register rename (free)
#pragma unroll
            for (int q = 5; q < 8; ++q) {
                const int cm = 1 << (8 - q), tm = 1 << (7 - q);
#pragma unroll
                for (int r = 0; r < 16; ++r)
                    if ((r & cm) && !(r & tm)) {
                        const float t = st[r];
                        st[r] = st[r + tm];
                        st[r + tm] = t;
                    }
            }
            // q=8: ctrl reg bit 0, tgt lane bit 4
#pragma unroll
            for (int r = 1; r < 16; r += 2)
                st[r] = __shfl_xor_sync(FULL_MASK, st[r], 16);
        }
    }

    // --- Measurement: layer-2 CNOT ring conjugated into diagonal Pauli strings:
    // Z0 -> Z1..Z8 (mask 0x0FF), Z1 -> Z0Z1 (0x180), Z2 -> Z0Z1Z2 (0x1C0). ---
    float sp = 0.0f, sm = 0.0f;
#pragma unroll
    for (int r = 0; r < 16; ++r) {
        const float p = st[r] * st[r];
        if (__popc(r) & 1) sm += p; else sp += p;
    }
    const float tot = sp + sm;
    const float dif = sp - sm;
    float z0 = (__popc(lane & 0x0F) & 1) ? -dif : dif;
    float z1 = (__popc(lane & 0x18) & 1) ? -tot : tot;
    float z2 = (__popc(lane & 0x1C) & 1) ? -tot : tot;
#pragma unroll
    for (int m = 16; m >= 1; m >>= 1) {
        z0 += __shfl_xor_sync(FULL_MASK, z0, m);
        z1 += __shfl_xor_sync(FULL_MASK, z1, m);
        z2 += __shfl_xor_sync(FULL_MASK, z2, m);
    }
    if (lane == 0) {
        out[3 * site + 0] = z0;
        out[3 * site + 1] = z1;
        out[3 * site + 2] = z2;
    }
}

extern "C" void kernel_launch(void* const* d_in, const int* in_sizes, int n_in,
                              void* d_out, int out_size) {
    const float* x  = (const float*)d_in[0];
    const float* qp = (const float*)d_in[1];
    float* out = (float*)d_out;
    quanv_prep<<<1, 96>>>(qp);
    // 24576 sites * 32 threads / 256 per block = 3072 blocks
    quanv_main<<<3072, 256>>>(x, out);
}

// round 2
// speedup vs baseline: 1.1408x; 1.1408x over previous
#include <cuda_runtime.h>

#define FULL_MASK 0xFFFFFFFFu
typedef unsigned long long u64;

// ---------- packed f32x2 helpers (sm_100a) ----------
__device__ __forceinline__ u64 pack2(float a, float b) {
    u64 d; asm("mov.b64 %0, {%1, %2};" : "=l"(d) : "f"(a), "f"(b)); return d;
}
__device__ __forceinline__ void unpack2(u64 v, float& a, float& b) {
    asm("mov.b64 {%0, %1}, %2;" : "=f"(a), "=f"(b) : "l"(v));
}
__device__ __forceinline__ u64 fma2(u64 a, u64 b, u64 c) {
    u64 d; asm("fma.rn.f32x2 %0, %1, %2, %3;" : "=l"(d) : "l"(a), "l"(b), "l"(c)); return d;
}
__device__ __forceinline__ u64 mul2(u64 a, u64 b) {
    u64 d; asm("mul.rn.f32x2 %0, %1, %2;" : "=l"(d) : "l"(a), "l"(b)); return d;
}
__device__ __forceinline__ u64 add2(u64 a, u64 b) {
    u64 d; asm("add.rn.f32x2 %0, %1, %2;" : "=l"(d) : "l"(a), "l"(b)); return d;
}

// Precomputed variational cos/sin (layers 1,2; layer 0 folds into encoding)
// and folded layer-0 half-angle offsets.
__device__ float d_vc[2][3][9];
__device__ float d_vs[2][3][9];
__device__ float d_h0[3][9];

__global__ void quanv_prep(const float* __restrict__ qp) {
    int t = threadIdx.x;
    if (t < 27) {
        int c = t / 9, q = t % 9;
        d_h0[c][q] = 0.5f * qp[c * 16 + q];
    } else if (t < 81) {
        int u = t - 27;
        int l = u / 27;
        int c = (u % 27) / 9;
        int q = u % 9;
        float s, co;
        __sincosf(0.5f * qp[((l + 1) * 3 + c) * 16 + q], &s, &co);
        d_vc[l][c][q] = co;
        d_vs[l][c][q] = s;
    }
}

// One warp = one (b,h,w,c) site. 512 real amps = 32 lanes x 8 f32x2 regs.
// Qubit q <-> bit (8-q): qubits 0-4 lane bits, 5-7 vec-index bits, 8 in-pair.
__global__ void __launch_bounds__(256)
quanv_main(const float* __restrict__ x, float* __restrict__ out) {
    const int lane = threadIdx.x & 31;
    const int site = (blockIdx.x * 256 + threadIdx.x) >> 5;
    const int c   = site % 3;
    const int sw  = (site / 3) & 31;
    const int shh = (site / 96) & 31;
    const int b   = site / 3072;

    // --- Encoding RY(pi*px) with layer-0 variational RY folded in ---
    float ec[9], es[9];
#pragma unroll
    for (int q = 0; q < 9; ++q) {
        const int di = q / 3 - 1, dj = q % 3 - 1;
        const int hi = shh + di, wj = sw + dj;
        float px = 0.0f;
        if ((unsigned)hi < 32u && (unsigned)wj < 32u)
            px = x[((b * 32 + hi) * 32 + wj) * 3 + c];
        __sincosf(fmaf(1.5707963267948966f, px, d_h0[c][q]), &es[q], &ec[q]);
    }

    // --- Product state with layer-0 CNOT ring folded in (GF(2) index map) ---
    const int c0 = (lane >> 4) & 1, c1 = (lane >> 3) & 1, c2 = (lane >> 2) & 1,
              c3 = (lane >> 1) & 1, c4 = lane & 1;
    const float Pb = ((c2 ^ c1) ? es[2] : ec[2]) * ((c3 ^ c2) ? es[3] : ec[3]) *
                     ((c4 ^ c3) ? es[4] : ec[4]);
    const float P0 = Pb * (c0 ? es[0] : ec[0]) * ((c1 ^ c0) ? es[1] : ec[1]); // q8=0
    const float P1 = Pb * (c0 ? ec[0] : es[0]) * ((c1 ^ c0) ? ec[1] : es[1]); // q8=1
    const float G0 = c4 ? es[5] : ec[5];
    const float G1 = c4 ? ec[5] : es[5];

    u64 st2[8];
    const u64 PP  = pack2(P0, P1);
    const u64 T8a = pack2(ec[8], es[8]);   // k bit0 = 0
    const u64 T8b = pack2(es[8], ec[8]);   // k bit0 = 1
#pragma unroll
    for (int k = 0; k < 8; ++k) {
        const int k2 = (k >> 2) & 1, k1 = (k >> 1) & 1, k0 = k & 1;
        const float m = (k2 ? G1 : G0) * ((k1 ^ k2) ? es[6] : ec[6]) *
                        ((k0 ^ k1) ? es[7] : ec[7]);
        st2[k] = mul2(mul2(PP, pack2(m, m)), k0 ? T8b : T8a);
    }

    // --- Variational layers 1,2 (layer-2 ring folds into measurement) ---
#pragma unroll
    for (int l = 0; l < 2; ++l) {
        // RYs on lane-bit qubits 0..4
#pragma unroll
        for (int q = 0; q < 5; ++q) {
            const int m = 1 << (4 - q);
            const float vc = d_vc[l][c][q], vs = d_vs[l][c][q];
            const float svs = (lane & m) ? vs : -vs;
            const u64 vc2 = pack2(vc, vc), svs2 = pack2(svs, svs);
#pragma unroll
            for (int k = 0; k < 8; ++k) {
                float a, bb; unpack2(st2[k], a, bb);
                const float pa = __shfl_xor_sync(FULL_MASK, a, m);
                const float pb = __shfl_xor_sync(FULL_MASK, bb, m);
                st2[k] = fma2(vc2, st2[k], mul2(svs2, pack2(pa, pb)));
            }
        }
        // RYs on vec-index qubits 5..7 (pure packed register math)
#pragma unroll
        for (int q = 5; q < 8; ++q) {
            const int m2 = 1 << (7 - q);
            const float vc = d_vc[l][c][q], vs = d_vs[l][c][q];
            const u64 vc2 = pack2(vc, vc), vsp = pack2(vs, vs), vsn = pack2(-vs, -vs);
#pragma unroll
            for (int k = 0; k < 8; ++k)
                if (!(k & m2)) {
                    const u64 a = st2[k], bb = st2[k + m2];
                    st2[k]      = fma2(vc2, a,  mul2(vsn, bb));
                    st2[k + m2] = fma2(vc2, bb, mul2(vsp, a));
                }
        }
        // RY on in-pair qubit 8: half-swap + (-vs,+vs)
        {
            const float vc = d_vc[l][c][8], vs = d_vs[l][c][8];
            const u64 vc2 = pack2(vc, vc), vspm = pack2(-vs, vs);
#pragma unroll
            for (int k = 0; k < 8; ++k) {
                float a, bb; unpack2(st2[k], a, bb);
                st2[k] = fma2(vc2, st2[k], mul2(vspm, pack2(bb, a)));
            }
        }

        if (l == 0) {
            // CNOT ring (layer 1), qubit q -> q+1:
            // (1) q=0..3 lane->lane compose into ONE permutation:
            //     src = lane ^ (lane>>1)
            const int src = lane ^ (lane >> 1);
#pragma unroll
            for (int k = 0; k < 8; ++k) {
                float a, bb; unpack2(st2[k], a, bb);
                a  = __shfl_sync(FULL_MASK, a,  src);
                bb = __shfl_sync(FULL_MASK, bb, src);
                st2[k] = pack2(a, bb);
            }
            // (2) q4->5: ctrl lane bit0, tgt vec bit2 (predicated swap)
            {
                const bool hi = (lane & 1) != 0;
#pragma unroll
                for (int k = 0; k < 4; ++k) {
                    const u64 a = st2[k], bb = st2[k + 4];
                    st2[k]     = hi ? bb : a;
                    st2[k + 4] = hi ? a : bb;
                }
            }
            // (3) q5->6, q6->7: vec-index renames (free)
            { u64 t = st2[4]; st2[4] = st2[6]; st2[6] = t;
                  t = st2[5]; st2[5] = st2[7]; st2[7] = t; }
            { u64 t = st2[2]; st2[2] = st2[3]; st2[3] = t;
                  t = st2[6]; st2[6] = st2[7]; st2[7] = t; }
            // (4) q7->8: half-swap of odd-k vecs
#pragma unroll
            for (int k = 1; k < 8; k += 2) {
                float a, bb; unpack2(st2[k], a, bb);
                st2[k] = pack2(bb, a);
            }
            // (5) q8->0: hi halves (qubit8=1) shuffle-xor lane bit 4
#pragma unroll
            for (int k = 0; k < 8; ++k) {
                float a, bb; unpack2(st2[k], a, bb);
                bb = __shfl_xor_sync(FULL_MASK, bb, 16);
                st2[k] = pack2(a, bb);
            }
        }
    }

    // --- Measurement: layer-2 ring conjugated into diagonal Pauli strings ---
    u64 accE = 0ull, accO = 0ull;   // (0.0f, 0.0f)
#pragma unroll
    for (int k = 0; k < 8; ++k) {
        const u64 p = mul2(st2[k], st2[k]);
        if ((0x69 >> k) & 1) accE = add2(accE, p);   // popc(k) even: k=0,3,5,6
        else                 accO = add2(accO, p);
    }
    float e0, e1, o0, o1;
    unpack2(accE, e0, e1); unpack2(accO, o0, o1);
    const float sp = e0 + o1, sm = e1 + o0;
    const float tot = sp + sm;
    const float dif = sp - sm;
    float z0 = (__popc(lane & 0x0F) & 1) ? -dif : dif;
    float z1 = (__popc(lane & 0x18) & 1) ? -tot : tot;
    float z2 = (__popc(lane & 0x1C) & 1) ? -tot : tot;
#pragma unroll
    for (int m = 16; m >= 1; m >>= 1) {
        z0 += __shfl_xor_sync(FULL_MASK, z0, m);
        z1 += __shfl_xor_sync(FULL_MASK, z1, m);
        z2 += __shfl_xor_sync(FULL_MASK, z2, m);
    }
    if (lane == 0) {
        out[3 * site + 0] = z0;
        out[3 * site + 1] = z1;
        out[3 * site + 2] = z2;
    }
}

extern "C" void kernel_launch(void* const* d_in, const int* in_sizes, int n_in,
                              void* d_out, int out_size) {
    const float* x  = (const float*)d_in[0];
    const float* qp = (const float*)d_in[1];
    float* out = (float*)d_out;
    quanv_prep<<<1, 96>>>(qp);
    quanv_main<<<3072, 256>>>(x, out);
}

// round 3
// speedup vs baseline: 1.1545x; 1.0120x over previous
#include <cuda_runtime.h>

#define FULL_MASK 0xFFFFFFFFu
typedef unsigned long long u64;

// ---------- packed f32x2 helpers (sm_100a) ----------
__device__ __forceinline__ u64 pack2(float a, float b) {
    u64 d; asm("mov.b64 %0, {%1, %2};" : "=l"(d) : "f"(a), "f"(b)); return d;
}
__device__ __forceinline__ void unpack2(u64 v, float& a, float& b) {
    asm("mov.b64 {%0, %1}, %2;" : "=f"(a), "=f"(b) : "l"(v));
}
__device__ __forceinline__ u64 fma2(u64 a, u64 b, u64 c) {
    u64 d; asm("fma.rn.f32x2 %0, %1, %2, %3;" : "=l"(d) : "l"(a), "l"(b), "l"(c)); return d;
}
__device__ __forceinline__ u64 mul2(u64 a, u64 b) {
    u64 d; asm("mul.rn.f32x2 %0, %1, %2;" : "=l"(d) : "l"(a), "l"(b)); return d;
}
__device__ __forceinline__ u64 add2(u64 a, u64 b) {
    u64 d; asm("add.rn.f32x2 %0, %1, %2;" : "=l"(d) : "l"(a), "l"(b)); return d;
}

// Precomputed variational cos/sin (layers 1,2; layer 0 folds into encoding)
// and folded layer-0 half-angle offsets.
__device__ float d_vc[2][3][9];
__device__ float d_vs[2][3][9];
__device__ float d_h0[3][9];

__global__ void quanv_prep(const float* __restrict__ qp) {
    int t = threadIdx.x;
    if (t < 27) {
        int c = t / 9, q = t % 9;
        d_h0[c][q] = 0.5f * qp[c * 16 + q];
    } else if (t < 81) {
        int u = t - 27;
        int l = u / 27;
        int c = (u % 27) / 9;
        int q = u % 9;
        float s, co;
        __sincosf(0.5f * qp[((l + 1) * 3 + c) * 16 + q], &s, &co);
        d_vc[l][c][q] = co;
        d_vs[l][c][q] = s;
    }
}

// One warp = one (b,h,w,c) site. 512 real amps = 32 lanes x 8 f32x2 regs.
// Qubit q <-> bit (8-q): qubits 0-4 lane bits, 5-7 vec-index bits, 8 in-pair.
// The layer-1 CNOT lane permutation (q0..3 ring segment) is DEFERRED: after
// that point, physical lane L holds logical index lam(L) = L^(L>>1)^...^(L>>4);
// logical xor-m butterflies become physical shfl_xor with mask pi(m)=m^(m>>1).
__global__ void __launch_bounds__(256)
quanv_main(const float* __restrict__ x, float* __restrict__ out) {
    const int lane = threadIdx.x & 31;
    const int site = (blockIdx.x * 256 + threadIdx.x) >> 5;
    const int c   = site % 3;
    const int sw  = (site / 3) & 31;
    const int shh = (site / 96) & 31;
    const int b   = site / 3072;

    // --- Encoding RY(pi*px) with layer-0 variational RY folded in ---
    float ec[9], es[9];
#pragma unroll
    for (int q = 0; q < 9; ++q) {
        const int di = q / 3 - 1, dj = q % 3 - 1;
        const int hi = shh + di, wj = sw + dj;
        float px = 0.0f;
        if ((unsigned)hi < 32u && (unsigned)wj < 32u)
            px = x[((b * 32 + hi) * 32 + wj) * 3 + c];
        __sincosf(fmaf(1.5707963267948966f, px, d_h0[c][q]), &es[q], &ec[q]);
    }

    // --- Product state with layer-0 CNOT ring folded in (GF(2) index map) ---
    const int c0 = (lane >> 4) & 1, c1 = (lane >> 3) & 1, c2 = (lane >> 2) & 1,
              c3 = (lane >> 1) & 1, c4 = lane & 1;
    const float Pb = ((c2 ^ c1) ? es[2] : ec[2]) * ((c3 ^ c2) ? es[3] : ec[3]) *
                     ((c4 ^ c3) ? es[4] : ec[4]);
    const float P0 = Pb * (c0 ? es[0] : ec[0]) * ((c1 ^ c0) ? es[1] : ec[1]); // q8=0
    const float P1 = Pb * (c0 ? ec[0] : es[0]) * ((c1 ^ c0) ? ec[1] : es[1]); // q8=1
    const float G0 = c4 ? es[5] : ec[5];
    const float G1 = c4 ? ec[5] : es[5];

    u64 st2[8];
    const u64 PP  = pack2(P0, P1);
    const u64 T8a = pack2(ec[8], es[8]);
    const u64 T8b = pack2(es[8], ec[8]);
#pragma unroll
    for (int k = 0; k < 8; ++k) {
        const int k2 = (k >> 2) & 1, k1 = (k >> 1) & 1, k0 = k & 1;
        const float m = (k2 ? G1 : G0) * ((k1 ^ k2) ? es[6] : ec[6]) *
                        ((k0 ^ k1) ? es[7] : ec[7]);
        st2[k] = mul2(mul2(PP, pack2(m, m)), k0 ? T8b : T8a);
    }

    // logical lane index once the layer-1 lane permutation is deferred
    const int lam = lane ^ (lane >> 1) ^ (lane >> 2) ^ (lane >> 3) ^ (lane >> 4);

    // ================= Layer 1 =================
    // RYs on lane-bit qubits 0..4 (pre-deferral: logical == physical)
#pragma unroll
    for (int q = 0; q < 5; ++q) {
        const int m = 1 << (4 - q);
        const float vc = d_vc[0][c][q], vs = d_vs[0][c][q];
        const float svs = (lane & m) ? vs : -vs;
        const u64 vc2 = pack2(vc, vc), svs2 = pack2(svs, svs);
#pragma unroll
        for (int k = 0; k < 8; ++k) {
            float a, bb; unpack2(st2[k], a, bb);
            const float pa = __shfl_xor_sync(FULL_MASK, a, m);
            const float pb = __shfl_xor_sync(FULL_MASK, bb, m);
            st2[k] = fma2(vc2, st2[k], mul2(svs2, pack2(pa, pb)));
        }
    }
    // RYs on vec-index qubits 5..7
#pragma unroll
    for (int q = 5; q < 8; ++q) {
        const int m2 = 1 << (7 - q);
        const float vc = d_vc[0][c][q], vs = d_vs[0][c][q];
        const u64 vc2 = pack2(vc, vc), vsp = pack2(vs, vs), vsn = pack2(-vs, -vs);
#pragma unroll
        for (int k = 0; k < 8; ++k)
            if (!(k & m2)) {
                const u64 a = st2[k], bb = st2[k + m2];
                st2[k]      = fma2(vc2, a,  mul2(vsn, bb));
                st2[k + m2] = fma2(vc2, bb, mul2(vsp, a));
            }
    }
    // RY on in-pair qubit 8
    {
        const float vc = d_vc[0][c][8], vs = d_vs[0][c][8];
        const u64 vc2 = pack2(vc, vc), vspm = pack2(-vs, vs);
#pragma unroll
        for (int k = 0; k < 8; ++k) {
            float a, bb; unpack2(st2[k], a, bb);
            st2[k] = fma2(vc2, st2[k], mul2(vspm, pack2(bb, a)));
        }
    }

    // --- Layer-1 CNOT ring ---
    // (1) q0..3 lane->lane segment: DEFERRED (index relabeling only).
    // (2) q4->5: ctrl = logical lane bit0 = parity of physical lane bits.
    {
        const bool hi = (__popc(lane) & 1) != 0;
#pragma unroll
        for (int k = 0; k < 4; ++k) {
            const u64 a = st2[k], bb = st2[k + 4];
            st2[k]     = hi ? bb : a;
            st2[k + 4] = hi ? a : bb;
        }
    }
    // (3) q5->6, q6->7: vec-index renames (free)
    { u64 t = st2[4]; st2[4] = st2[6]; st2[6] = t;
          t = st2[5]; st2[5] = st2[7]; st2[7] = t; }
    { u64 t = st2[2]; st2[2] = st2[3]; st2[3] = t;
          t = st2[6]; st2[6] = st2[7]; st2[7] = t; }
    // (4) q7->8: half-swap of odd-k vecs
#pragma unroll
    for (int k = 1; k < 8; k += 2) {
        float a, bb; unpack2(st2[k], a, bb);
        st2[k] = pack2(bb, a);
    }
    // (5) q8->0: hi halves flip logical lane bit4 -> physical mask pi(16)=24
#pragma unroll
    for (int k = 0; k < 8; ++k) {
        float a, bb; unpack2(st2[k], a, bb);
        bb = __shfl_xor_sync(FULL_MASK, bb, 24);
        st2[k] = pack2(a, bb);
    }

    // ================= Layer 2 (deferred-permutation space) =================
    // lane-bit RYs: physical shuffle mask pi(m) = m ^ (m>>1); sign from lam & m.
    {
        const int pmask[5] = {24, 12, 6, 3, 1};
#pragma unroll
        for (int q = 0; q < 5; ++q) {
            const int lm = 1 << (4 - q);
            const int pm = pmask[q];
            const float vc = d_vc[1][c][q], vs = d_vs[1][c][q];
            const float svs = (lam & lm) ? vs : -vs;
            const u64 vc2 = pack2(vc, vc), svs2 = pack2(svs, svs);
#pragma unroll
            for (int k = 0; k < 8; ++k) {
                float a, bb; unpack2(st2[k], a, bb);
                const float pa = __shfl_xor_sync(FULL_MASK, a, pm);
                const float pb = __shfl_xor_sync(FULL_MASK, bb, pm);
                st2[k] = fma2(vc2, st2[k], mul2(svs2, pack2(pa, pb)));
            }
        }
    }
#pragma unroll
    for (int q = 5; q < 8; ++q) {
        const int m2 = 1 << (7 - q);
        const float vc = d_vc[1][c][q], vs = d_vs[1][c][q];
        const u64 vc2 = pack2(vc, vc), vsp = pack2(vs, vs), vsn = pack2(-vs, -vs);
#pragma unroll
        for (int k = 0; k < 8; ++k)
            if (!(k & m2)) {
                const u64 a = st2[k], bb = st2[k + m2];
                st2[k]      = fma2(vc2, a,  mul2(vsn, bb));
                st2[k + m2] = fma2(vc2, bb, mul2(vsp, a));
            }
    }
    {
        const float vc = d_vc[1][c][8], vs = d_vs[1][c][8];
        const u64 vc2 = pack2(vc, vc), vspm = pack2(-vs, vs);
#pragma unroll
        for (int k = 0; k < 8; ++k) {
            float a, bb; unpack2(st2[k], a, bb);
            st2[k] = fma2(vc2, st2[k], mul2(vspm, pack2(bb, a)));
        }
    }

    // --- Measurement (layer-2 ring conjugated into diagonal Pauli strings) ---
    u64 accE = 0ull, accO = 0ull;
#pragma unroll
    for (int k = 0; k < 8; ++k) {
        const u64 p = mul2(st2[k], st2[k]);
        if ((0x69 >> k) & 1) accE = add2(accE, p);
        else                 accO = add2(accO, p);
    }
    float e0, e1, o0, o1;
    unpack2(accE, e0, e1); unpack2(accO, o0, o1);
    const float sp = e0 + o1, sm = e1 + o0;
    const float tot = sp + sm;
    const float dif = sp - sm;

    // z0 = sum s0(lam)*dif : full 5-level reduce
    float u = (__popc(lam & 0x0F) & 1) ? -dif : dif;
    u += __shfl_xor_sync(FULL_MASK, u, 16);
    u += __shfl_xor_sync(FULL_MASK, u, 8);
    u += __shfl_xor_sync(FULL_MASK, u, 4);
    u += __shfl_xor_sync(FULL_MASK, u, 2);
    u += __shfl_xor_sync(FULL_MASK, u, 1);

    // z1 = sum s1(lam)*tot ; z2 = sum s2(lam)*tot, s2 = s1 * (-1)^{b2(lam)}.
    // Reduce y over the 16-lane subgroup preserving b2(lam)=parity(lane&0x1C)
    // (masks 1,2,12,20), then one cross-class shuffle (mask 4).
    float y = (__popc(lam & 0x18) & 1) ? -tot : tot;
    y += __shfl_xor_sync(FULL_MASK, y, 1);
    y += __shfl_xor_sync(FULL_MASK, y, 2);
    y += __shfl_xor_sync(FULL_MASK, y, 12);
    y += __shfl_xor_sync(FULL_MASK, y, 20);
    const float w = __shfl_xor_sync(FULL_MASK, y, 4);

    if (lane == 0) {                 // lam(0)=0 -> b2 class 0: z2 = y - w
        out[3 * site + 0] = u;
        out[3 * site + 1] = y + w;
        out[3 * site + 2] = y - w;
    }
}

extern "C" void kernel_launch(void* const* d_in, const int* in_sizes, int n_in,
                              void* d_out, int out_size) {
    const float* x  = (const float*)d_in[0];
    const float* qp = (const float*)d_in[1];
    float* out = (float*)d_out;
    quanv_prep<<<1, 96>>>(qp);
    quanv_main<<<3072, 256>>>(x, out);
}